// round 2
// baseline (speedup 1.0000x reference)
#include <cuda_runtime.h>
#include <math.h>

#define Dm 64
#define Gm 320          // 5*D
#define NL 524288       // leaves
#define NLEVELS 19

// Scratch: all merged levels stored contiguously (levels 1..19, total N-1 rows)
// so per-level representative rows stay live for the summary pass.
__device__ float g_h[(NL - 1) * Dm];
__device__ float g_c[(NL - 1) * Dm];

#define TR 32           // output rows (pairs) per tile
#define RT 8            // rows per thread
#define CT 4            // cols per thread
#define NTHR 320        // (TR/RT) * (Gm/CT) = 4 * 80
#define HPAD 36         // padded row stride for sH (multiple of 4 floats, 16B-aligned rows)

__device__ __forceinline__ float sigm(float x) { return 1.0f / (1.0f + expf(-x)); }

// smem: sW[128*320] | sH[128*HPAD] | sG[TR*320]
#define MERGE_SMEM ((128 * 320 + 128 * HPAD + TR * 320) * sizeof(float))
#define SUM_SMEM ((128 * 320 + 64 + 64 + 320) * sizeof(float))

__global__ __launch_bounds__(NTHR, 1)
void merge_kernel(const float* __restrict__ h_in, const float* __restrict__ c_in,
                  float* __restrict__ h_out, float* __restrict__ c_out,
                  const float* __restrict__ Wl, const float* __restrict__ Wr,
                  const float* __restrict__ bias, int n_out)
{
    extern __shared__ float smem[];
    float* sW = smem;                  // [128][320]: rows 0..63 = Wl, 64..127 = Wr
    float* sH = sW + 128 * 320;        // [128][HPAD]: concat(hl, hr) transposed, k-major
    float* sG = sH + 128 * HPAD;       // [TR][320]: preactivations

    const int tid = threadIdx.x;
    const int cg = tid % (Gm / CT);    // 0..79
    const int rg = tid / (Gm / CT);    // 0..3
    const int c0 = cg * CT;
    const int r0 = rg * RT;

    // Load both weight matrices into smem once per block (grid-stride loop amortizes).
    for (int idx = tid; idx < 64 * Gm; idx += NTHR) {
        sW[idx] = Wl[idx];
        sW[64 * Gm + idx] = Wr[idx];
    }
    float bcol[CT];
#pragma unroll
    for (int i = 0; i < CT; ++i) bcol[i] = bias[c0 + i];
    __syncthreads();

    const int ntiles = (n_out + TR - 1) / TR;
    for (int tile = blockIdx.x; tile < ntiles; tile += gridDim.x) {
        const int j0 = tile * TR;

        // Stage input tile: sH[k][r] = k<64 ? h_in[2*(j0+r)][k] : h_in[2*(j0+r)+1][k-64]
        for (int idx = tid; idx < TR * 128; idx += NTHR) {
            const int r = idx >> 7;
            const int k = idx & 127;
            const int j = j0 + r;
            float v = 0.0f;
            if (j < n_out) {
                const int src = (k < 64) ? ((2 * j) * Dm + k)
                                         : ((2 * j + 1) * Dm + (k - 64));
                v = h_in[src];
            }
            sH[k * HPAD + r] = v;
        }
        __syncthreads();

        // Register-tiled GEMM: each thread accumulates RT x CT outputs.
        float acc[RT][CT];
#pragma unroll
        for (int r = 0; r < RT; ++r)
#pragma unroll
            for (int c = 0; c < CT; ++c) acc[r][c] = 0.0f;

#pragma unroll 4
        for (int k = 0; k < 128; ++k) {
            const float4 wv = *reinterpret_cast<const float4*>(&sW[k * Gm + c0]);
            const float4 h0 = *reinterpret_cast<const float4*>(&sH[k * HPAD + r0]);
            const float4 h1 = *reinterpret_cast<const float4*>(&sH[k * HPAD + r0 + 4]);
            const float hv[RT] = {h0.x, h0.y, h0.z, h0.w, h1.x, h1.y, h1.z, h1.w};
#pragma unroll
            for (int r = 0; r < RT; ++r) {
                acc[r][0] += hv[r] * wv.x;
                acc[r][1] += hv[r] * wv.y;
                acc[r][2] += hv[r] * wv.z;
                acc[r][3] += hv[r] * wv.w;
            }
        }

        // Stash preactivations (+bias) so the cell can gather all 5 gates per (row,d).
#pragma unroll
        for (int r = 0; r < RT; ++r) {
            float4 o;
            o.x = acc[r][0] + bcol[0];
            o.y = acc[r][1] + bcol[1];
            o.z = acc[r][2] + bcol[2];
            o.w = acc[r][3] + bcol[3];
            *reinterpret_cast<float4*>(&sG[(r0 + r) * Gm + c0]) = o;
        }
        __syncthreads();

        // Elementwise TreeLSTM cell: gates i,o,u,fl,fr at cols d,64+d,128+d,192+d,256+d.
        for (int idx = tid; idx < TR * Dm; idx += NTHR) {
            const int r = idx >> 6;
            const int d = idx & 63;
            const int j = j0 + r;
            if (j < n_out) {
                const float* grow = &sG[r * Gm];
                const float gi = grow[d];
                const float go = grow[64 + d];
                const float gu = grow[128 + d];
                const float gfl = grow[192 + d];
                const float gfr = grow[256 + d];
                const float cl = c_in[(2 * j) * Dm + d];
                const float cr = c_in[(2 * j + 1) * Dm + d];
                const float c = sigm(gi) * tanhf(gu) + sigm(gfl) * cl + sigm(gfr) * cr;
                const float h = sigm(go) * tanhf(c);
                h_out[j * Dm + d] = h;
                c_out[j * Dm + d] = c;
            }
        }
        __syncthreads();
    }
}

// Single-block sequential summary fold over the 19 level representatives.
__global__ __launch_bounds__(NTHR, 1)
void summary_kernel(const float* __restrict__ h_bot, const float* __restrict__ c_bot,
                    const float* __restrict__ Wl, const float* __restrict__ Wr,
                    const float* __restrict__ bias, float* __restrict__ out)
{
    extern __shared__ float smem[];
    float* sW = smem;                // [128][320]
    float* ssh = sW + 128 * 320;     // [64] running summary h
    float* ssc = ssh + 64;           // [64] running summary c
    float* sg = ssc + 64;            // [320]

    const int tid = threadIdx.x;
    for (int idx = tid; idx < 64 * Gm; idx += NTHR) {
        sW[idx] = Wl[idx];
        sW[64 * Gm + idx] = Wr[idx];
    }
    if (tid < 64) {
        // Root = level 19 output = last stored row (offset NL-2).
        ssh[tid] = g_h[(long)(NL - 2) * Dm + tid];
        ssc[tid] = g_c[(long)(NL - 2) * Dm + tid];
    }
    __syncthreads();

    for (int level = NLEVELS - 1; level >= 0; --level) {
        const float* lh;
        const float* lc;
        if (level == 0) {
            lh = h_bot + (long)(NL - 1) * Dm;
            lc = c_bot + (long)(NL - 1) * Dm;
        } else {
            const int nl = NL >> level;
            const long off = (long)NL - (NL >> (level - 1));
            lh = g_h + (off + nl - 1) * Dm;
            lc = g_c + (off + nl - 1) * Dm;
        }
        // g[t] = b[t] + sum_k ssh[k]*Wl[k][t] + lh[k]*Wr[k][t]
        float acc = bias[tid];
#pragma unroll 8
        for (int k = 0; k < 64; ++k) {
            acc += ssh[k] * sW[k * Gm + tid];
            acc += lh[k] * sW[(64 + k) * Gm + tid];
        }
        sg[tid] = acc;
        __syncthreads();
        if (tid < 64) {
            const float c = sigm(sg[tid]) * tanhf(sg[128 + tid])
                          + sigm(sg[192 + tid]) * ssc[tid]
                          + sigm(sg[256 + tid]) * lc[tid];
            const float h = sigm(sg[64 + tid]) * tanhf(c);
            ssc[tid] = c;
            ssh[tid] = h;
        }
        __syncthreads();
    }
    if (tid < 64) {
        out[tid] = ssh[tid];
        out[64 + tid] = ssc[tid];
    }
}

extern "C" void kernel_launch(void* const* d_in, const int* in_sizes, int n_in,
                              void* d_out, int out_size)
{
    const float* h_bot = (const float*)d_in[0];
    const float* c_bot = (const float*)d_in[1];
    const float* mWl = (const float*)d_in[2];
    const float* mWr = (const float*)d_in[3];
    const float* mb = (const float*)d_in[4];
    const float* sWl = (const float*)d_in[5];
    const float* sWr = (const float*)d_in[6];
    const float* sb = (const float*)d_in[7];
    float* out = (float*)d_out;

    cudaFuncSetAttribute(merge_kernel, cudaFuncAttributeMaxDynamicSharedMemorySize,
                         (int)MERGE_SMEM);
    cudaFuncSetAttribute(summary_kernel, cudaFuncAttributeMaxDynamicSharedMemorySize,
                         (int)SUM_SMEM);

    void* gh_p = nullptr;
    void* gc_p = nullptr;
    cudaGetSymbolAddress(&gh_p, g_h);
    cudaGetSymbolAddress(&gc_p, g_c);
    float* gh = (float*)gh_p;
    float* gc = (float*)gc_p;

    const float* hin = h_bot;
    const float* cin = c_bot;
    for (int l = 1; l <= NLEVELS; ++l) {
        const int n_out = NL >> l;
        const long off = (long)NL - (NL >> (l - 1));
        float* hout = gh + off * Dm;
        float* cout = gc + off * Dm;
        const int ntiles = (n_out + TR - 1) / TR;
        const int grid = ntiles < 148 ? ntiles : 148;
        merge_kernel<<<grid, NTHR, MERGE_SMEM>>>(hin, cin, hout, cout, mWl, mWr, mb, n_out);
        hin = hout;
        cin = cout;
    }
    summary_kernel<<<1, NTHR, SUM_SMEM>>>(h_bot, c_bot, sWl, sWr, sb, out);
}

// round 4
// speedup vs baseline: 2.5759x; 2.5759x over previous
#include <cuda_runtime.h>
#include <cuda_bf16.h>
#include <math.h>
#include <stdint.h>

#define Dm 64
#define Gm 320          // 5*D
#define NL 524288
#define NLEVELS 19
#define TILE 128        // output rows per block tile

// Level outputs stored contiguously (levels 1..19, N-1 rows) so per-level
// representative rows stay live for the summary pass.
__device__ float g_h[(NL - 1) * Dm];
__device__ float g_c[(NL - 1) * Dm];

// Weight fragments, pre-split bf16 hi/lo, in mma.sync B-fragment order:
// index [kt(8)][dw(2)][gate(5)][sub(4)][lane(32)] -> uint4{b0hi,b1hi,b0lo,b1lo}
// B[k][n] = Wl[k][n] (k<64) else Wr[k-64][n];  n = gate*64 + dw*32 + sub*8 + lane/4,
// k = 16*kt + 2*(lane%4) (+1 in-word, +8 for b1).
#define NFRAG (8 * 2 * 5 * 4 * 32)      // 10240 uint4 = 160 KB
__device__ __align__(16) uint4 g_Bfrag[NFRAG];

#define MERGE_SMEM (NFRAG * 16 + Gm * 4)

__device__ __forceinline__ void split2(float a, float b, uint32_t& hi, uint32_t& lo) {
    __nv_bfloat16 ha = __float2bfloat16(a), hb = __float2bfloat16(b);
    __nv_bfloat16 la = __float2bfloat16(a - __bfloat162float(ha));
    __nv_bfloat16 lb = __float2bfloat16(b - __bfloat162float(hb));
    hi = ((uint32_t)__bfloat16_as_ushort(hb) << 16) | (uint32_t)__bfloat16_as_ushort(ha);
    lo = ((uint32_t)__bfloat16_as_ushort(lb) << 16) | (uint32_t)__bfloat16_as_ushort(la);
}

__device__ __forceinline__ float tanh_ap(float x) {
    float y;
    asm("tanh.approx.f32 %0, %1;" : "=f"(y) : "f"(x));
    return y;
}
__device__ __forceinline__ float sigm_ap(float x) {
    return 0.5f * tanh_ap(0.5f * x) + 0.5f;   // 1 MUFU + 2 FMA
}

__device__ __forceinline__ void mma_bf16(float* d, const uint32_t* a, uint32_t b0, uint32_t b1) {
    asm volatile(
        "mma.sync.aligned.m16n8k16.row.col.f32.bf16.bf16.f32 "
        "{%0,%1,%2,%3}, {%4,%5,%6,%7}, {%8,%9}, {%0,%1,%2,%3};"
        : "+f"(d[0]), "+f"(d[1]), "+f"(d[2]), "+f"(d[3])
        : "r"(a[0]), "r"(a[1]), "r"(a[2]), "r"(a[3]), "r"(b0), "r"(b1));
}

// Build the fragment-ordered split weight image once per launch.
__global__ void prep_Bfrag(const float* __restrict__ Wl, const float* __restrict__ Wr)
{
    const int idx = blockIdx.x * blockDim.x + threadIdx.x;
    if (idx >= NFRAG) return;
    const int lane = idx & 31;
    int t = idx >> 5;                  // (((kt*2+dw)*5+g)*4+sub)
    const int sub = t & 3; t >>= 2;
    const int g = t % 5; t /= 5;
    const int dw = t & 1;
    const int kt = t >> 1;
    const int n = g * 64 + dw * 32 + sub * 8 + (lane >> 2);
    const int k0 = kt * 16 + 2 * (lane & 3);

    auto W = [&](int k) -> float {
        return (k < 64) ? Wl[k * Gm + n] : Wr[(k - 64) * Gm + n];
    };
    uint32_t b0h, b0l, b1h, b1l;
    split2(W(k0), W(k0 + 1), b0h, b0l);
    split2(W(k0 + 8), W(k0 + 9), b1h, b1l);
    g_Bfrag[idx] = make_uint4(b0h, b1h, b0l, b1l);
}

// One merge level: out[j] = cell(h_in[2j], h_in[2j+1]), j in [0, n_out).
// Key layout fact: A row j's 128 features (concat of child rows 2j, 2j+1) are
// CONTIGUOUS in h_in at offset j*128. Same for c_in (cl at +d, cr at +64+d).
__global__ __launch_bounds__(256, 1)
void merge_mma(const float* __restrict__ h_in, const float* __restrict__ c_in,
               float* __restrict__ h_out, float* __restrict__ c_out,
               const float* __restrict__ bias, int n_out)
{
    extern __shared__ uint4 smv[];                 // [NFRAG] frags, then bias
    float* sbias = (float*)(smv + NFRAG);

    const int tid = threadIdx.x;
    for (int i = tid; i < NFRAG; i += 256) smv[i] = g_Bfrag[i];
    for (int i = tid; i < Gm; i += 256) sbias[i] = bias[i];
    __syncthreads();

    const int w = tid >> 5;
    const int lane = tid & 31;
    const int mw = w & 3;          // row-warp: 32 rows each
    const int dw = w >> 2;         // d-warp: 32 of 64 d-cols
    const int gID = lane >> 2;     // 0..7 row within fragment
    const int qid = lane & 3;      // 0..3 col quad

    const int ntiles = (n_out + TILE - 1) / TILE;

    for (int tile = blockIdx.x; tile < ntiles; tile += gridDim.x) {
        const int j0 = tile * TILE + mw * 32;

        float acc[2][20][4];
#pragma unroll
        for (int mt = 0; mt < 2; ++mt)
#pragma unroll
            for (int nt = 0; nt < 20; ++nt)
#pragma unroll
                for (int r = 0; r < 4; ++r) acc[mt][nt][r] = 0.0f;

        const int ja0 = j0 + gID;          // mt0, rows ja0, ja0+8
        const int ja1 = j0 + 16 + gID;     // mt1
        const bool v00 = (ja0 < n_out), v01 = (ja0 + 8 < n_out);
        const bool v10 = (ja1 < n_out), v11 = (ja1 + 8 < n_out);
        const float* a00 = h_in + (size_t)ja0 * 128;
        const float* a01 = h_in + (size_t)(ja0 + 8) * 128;
        const float* a10 = h_in + (size_t)ja1 * 128;
        const float* a11 = h_in + (size_t)(ja1 + 8) * 128;

#pragma unroll 1
        for (int kt = 0; kt < 8; ++kt) {
            const int o = kt * 16 + 2 * qid;
            uint32_t ah[2][4], al[2][4];
            // a0:(r,o) a1:(r+8,o) a2:(r,o+8) a3:(r+8,o+8)
            {
                float2 z = make_float2(0.f, 0.f);
                float2 f0 = v00 ? *(const float2*)(a00 + o) : z;
                float2 f1 = v01 ? *(const float2*)(a01 + o) : z;
                float2 f2 = v00 ? *(const float2*)(a00 + o + 8) : z;
                float2 f3 = v01 ? *(const float2*)(a01 + o + 8) : z;
                split2(f0.x, f0.y, ah[0][0], al[0][0]);
                split2(f1.x, f1.y, ah[0][1], al[0][1]);
                split2(f2.x, f2.y, ah[0][2], al[0][2]);
                split2(f3.x, f3.y, ah[0][3], al[0][3]);
                f0 = v10 ? *(const float2*)(a10 + o) : z;
                f1 = v11 ? *(const float2*)(a11 + o) : z;
                f2 = v10 ? *(const float2*)(a10 + o + 8) : z;
                f3 = v11 ? *(const float2*)(a11 + o + 8) : z;
                split2(f0.x, f0.y, ah[1][0], al[1][0]);
                split2(f1.x, f1.y, ah[1][1], al[1][1]);
                split2(f2.x, f2.y, ah[1][2], al[1][2]);
                split2(f3.x, f3.y, ah[1][3], al[1][3]);
            }
            const uint4* bp = smv + ((kt * 2 + dw) * 20) * 32 + lane;
#pragma unroll
            for (int nt = 0; nt < 20; ++nt) {
                const uint4 bb = bp[nt * 32];
                mma_bf16(acc[0][nt], ah[0], bb.x, bb.y);   // Ahi*Bhi
                mma_bf16(acc[1][nt], ah[1], bb.x, bb.y);
                mma_bf16(acc[0][nt], ah[0], bb.z, bb.w);   // Ahi*Blo
                mma_bf16(acc[1][nt], ah[1], bb.z, bb.w);
                mma_bf16(acc[0][nt], al[0], bb.x, bb.y);   // Alo*Bhi
                mma_bf16(acc[1][nt], al[1], bb.x, bb.y);
            }
        }

        // Epilogue: cell per element; gates for (row,d) live in this thread.
#pragma unroll
        for (int mt = 0; mt < 2; ++mt) {
            const int jb = j0 + mt * 16 + gID;
#pragma unroll
            for (int half = 0; half < 2; ++half) {
                const int j = jb + 8 * half;
                if (j >= n_out) continue;
                const float* cbase = c_in + (size_t)j * 128;
#pragma unroll
                for (int sub = 0; sub < 4; ++sub) {
                    const int d = dw * 32 + sub * 8 + 2 * qid;
                    const float2 cl = *(const float2*)(cbase + d);
                    const float2 cr = *(const float2*)(cbase + 64 + d);
                    float hx[2], cx[2];
#pragma unroll
                    for (int e = 0; e < 2; ++e) {
                        const int ri = 2 * half + e;
                        const float gi  = acc[mt][0 * 4 + sub][ri] + sbias[d + e];
                        const float go  = acc[mt][1 * 4 + sub][ri] + sbias[64 + d + e];
                        const float gu  = acc[mt][2 * 4 + sub][ri] + sbias[128 + d + e];
                        const float gfl = acc[mt][3 * 4 + sub][ri] + sbias[192 + d + e];
                        const float gfr = acc[mt][4 * 4 + sub][ri] + sbias[256 + d + e];
                        const float cle = e ? cl.y : cl.x;
                        const float cre = e ? cr.y : cr.x;
                        const float c = sigm_ap(gi) * tanh_ap(gu)
                                      + sigm_ap(gfl) * cle + sigm_ap(gfr) * cre;
                        cx[e] = c;
                        hx[e] = sigm_ap(go) * tanh_ap(c);
                    }
                    *(float2*)(h_out + (size_t)j * Dm + d) = make_float2(hx[0], hx[1]);
                    *(float2*)(c_out + (size_t)j * Dm + d) = make_float2(cx[0], cx[1]);
                }
            }
        }
    }
}

// ---------------- fp32 summary fold (19 sequential tiny cells) ----------------
#define SNTHR 320
#define SUM_SMEM ((128 * 320 + 64 + 64 + 320) * sizeof(float))

__device__ __forceinline__ float sigma_e(float x) { return 1.0f / (1.0f + expf(-x)); }

__global__ __launch_bounds__(SNTHR, 1)
void summary_kernel(const float* __restrict__ h_bot, const float* __restrict__ c_bot,
                    const float* __restrict__ Wl, const float* __restrict__ Wr,
                    const float* __restrict__ bias, float* __restrict__ out)
{
    extern __shared__ float smemf[];
    float* sW = smemf;               // [128][320]
    float* ssh = sW + 128 * 320;
    float* ssc = ssh + 64;
    float* sg = ssc + 64;

    const int tid = threadIdx.x;
    for (int idx = tid; idx < 64 * Gm; idx += SNTHR) {
        sW[idx] = Wl[idx];
        sW[64 * Gm + idx] = Wr[idx];
    }
    if (tid < 64) {
        ssh[tid] = g_h[(long)(NL - 2) * Dm + tid];
        ssc[tid] = g_c[(long)(NL - 2) * Dm + tid];
    }
    __syncthreads();

    for (int level = NLEVELS - 1; level >= 0; --level) {
        const float* lh;
        const float* lc;
        if (level == 0) {
            lh = h_bot + (long)(NL - 1) * Dm;
            lc = c_bot + (long)(NL - 1) * Dm;
        } else {
            const int nl = NL >> level;
            const long off = (long)NL - (NL >> (level - 1));
            lh = g_h + (off + nl - 1) * Dm;
            lc = g_c + (off + nl - 1) * Dm;
        }
        float acc = bias[tid];
#pragma unroll 8
        for (int k = 0; k < 64; ++k) {
            acc += ssh[k] * sW[k * Gm + tid];
            acc += lh[k] * sW[(64 + k) * Gm + tid];
        }
        sg[tid] = acc;
        __syncthreads();
        if (tid < 64) {
            const float c = sigma_e(sg[tid]) * tanhf(sg[128 + tid])
                          + sigma_e(sg[192 + tid]) * ssc[tid]
                          + sigma_e(sg[256 + tid]) * lc[tid];
            const float h = sigma_e(sg[64 + tid]) * tanhf(c);
            ssc[tid] = c;
            ssh[tid] = h;
        }
        __syncthreads();
    }
    if (tid < 64) {
        out[tid] = ssh[tid];
        out[64 + tid] = ssc[tid];
    }
}

extern "C" void kernel_launch(void* const* d_in, const int* in_sizes, int n_in,
                              void* d_out, int out_size)
{
    const float* h_bot = (const float*)d_in[0];
    const float* c_bot = (const float*)d_in[1];
    const float* mWl = (const float*)d_in[2];
    const float* mWr = (const float*)d_in[3];
    const float* mb = (const float*)d_in[4];
    const float* sWl = (const float*)d_in[5];
    const float* sWr = (const float*)d_in[6];
    const float* sb = (const float*)d_in[7];
    float* out = (float*)d_out;

    cudaFuncSetAttribute(merge_mma, cudaFuncAttributeMaxDynamicSharedMemorySize, (int)MERGE_SMEM);
    cudaFuncSetAttribute(summary_kernel, cudaFuncAttributeMaxDynamicSharedMemorySize, (int)SUM_SMEM);

    void* gh_p = nullptr; void* gc_p = nullptr;
    cudaGetSymbolAddress(&gh_p, g_h);
    cudaGetSymbolAddress(&gc_p, g_c);
    float* gh = (float*)gh_p;
    float* gc = (float*)gc_p;

    prep_Bfrag<<<(NFRAG + 255) / 256, 256>>>(mWl, mWr);

    const float* hin = h_bot;
    const float* cin = c_bot;
    for (int l = 1; l <= NLEVELS; ++l) {
        const int n_out = NL >> l;
        const long off = (long)NL - (NL >> (l - 1));
        float* hout = gh + off * Dm;
        float* cout = gc + off * Dm;
        const int ntiles = (n_out + TILE - 1) / TILE;
        const int grid = ntiles < 148 ? ntiles : 148;
        merge_mma<<<grid, 256, MERGE_SMEM>>>(hin, cin, hout, cout, mb, n_out);
        hin = hout;
        cin = cout;
    }
    summary_kernel<<<1, SNTHR, SUM_SMEM>>>(h_bot, c_bot, sWl, sWr, sb, out);
}